// round 9
// baseline (speedup 1.0000x reference)
#include <cuda_runtime.h>
#include <math.h>
#include <stdint.h>

#define BB 8
#define LL 4096
#define DD 256
#define ML (BB*LL)

// ---------------- scratch (no allocations allowed) ----------------
__device__ float g_q[ML*DD];
__device__ float g_k[ML*DD];
__device__ float g_v[ML*DD];
__device__ float g_attn[ML*DD];
__device__ float g_t[ML*DD];
__device__ int   g_lens[BB];
__device__ float g_psum[128*DD];
__device__ float g_psq[128*DD];
__device__ float g_mean[DD];
__device__ float g_rstd[DD];

// ---------------- mask -> per-batch length ----------------
// mask rows are prefix masks (arange < len), len in [L/2, L].
// Dtype detection: if byte 1 of the buffer == 1 -> 1-byte bool/uint8 layout
// (mask[0][1] is true since len>=2048). Otherwise 4-byte elements (int32 or
// float32: any nonzero 32-bit pattern is truthy).
__global__ void lens_kernel(const void* maskp){
    const unsigned char* mb = (const unsigned char*)maskp;
    const int b = blockIdx.x;
    const bool bytemode = (mb[1] == 1);
    __shared__ int sh[256];
    int cnt = 0;
    for (int i = threadIdx.x; i < LL; i += 256){
        bool valid;
        if (bytemode) valid = (mb[b*LL + i] != 0);
        else          valid = (((const int*)maskp)[b*LL + i] != 0);
        cnt += valid ? 1 : 0;
    }
    sh[threadIdx.x] = cnt;
    __syncthreads();
    for (int s = 128; s > 0; s >>= 1){
        if (threadIdx.x < s) sh[threadIdx.x] += sh[threadIdx.x + s];
        __syncthreads();
    }
    if (threadIdx.x == 0) g_lens[b] = sh[0];
}

// ---------------- SGEMM: C[M,256] = A[M,256] @ W[256,256] ----------------
// 64x64 block tile, BK=16, 256 threads, 4x4 micro-tile per thread.
__device__ __forceinline__ void sgemm_tile(const float* __restrict__ A,
                                           const float* __restrict__ W,
                                           float* __restrict__ C){
    __shared__ float As[16][68];   // As[kk][m]  (A transposed in smem)
    __shared__ float Bs[16][68];   // Bs[kk][n]
    const int tid = threadIdx.x;
    const int tx = tid & 15, ty = tid >> 4;
    const int m0 = blockIdx.y * 64, n0 = blockIdx.x * 64;
    const int ar = tid >> 2, ac = (tid & 3) * 4;     // A load: row, col4
    const int bk = tid >> 4, bn = (tid & 15) * 4;    // B load: krow, ncol4
    float acc[4][4] = {};
    for (int k0 = 0; k0 < 256; k0 += 16){
        float4 av = *(const float4*)(A + (size_t)(m0 + ar)*DD + k0 + ac);
        As[ac+0][ar] = av.x; As[ac+1][ar] = av.y;
        As[ac+2][ar] = av.z; As[ac+3][ar] = av.w;
        float4 bv = *(const float4*)(W + (size_t)(k0 + bk)*DD + n0 + bn);
        *(float4*)&Bs[bk][bn] = bv;
        __syncthreads();
        #pragma unroll
        for (int kk = 0; kk < 16; kk++){
            float4 a = *(const float4*)&As[kk][ty*4];
            float4 b = *(const float4*)&Bs[kk][tx*4];
            float a4[4] = {a.x, a.y, a.z, a.w};
            float b4[4] = {b.x, b.y, b.z, b.w};
            #pragma unroll
            for (int i = 0; i < 4; i++)
                #pragma unroll
                for (int j = 0; j < 4; j++)
                    acc[i][j] = fmaf(a4[i], b4[j], acc[i][j]);
        }
        __syncthreads();
    }
    #pragma unroll
    for (int i = 0; i < 4; i++){
        float4 o = make_float4(acc[i][0], acc[i][1], acc[i][2], acc[i][3]);
        *(float4*)(C + (size_t)(m0 + ty*4 + i)*DD + n0 + tx*4) = o;
    }
}

__global__ __launch_bounds__(256) void qkv_kernel(const float* __restrict__ X,
                                                  const float* __restrict__ Wq,
                                                  const float* __restrict__ Wk,
                                                  const float* __restrict__ Wv){
    const float* W; float* C;
    if (blockIdx.z == 0){ W = Wq; C = g_q; }
    else if (blockIdx.z == 1){ W = Wk; C = g_k; }
    else { W = Wv; C = g_v; }
    sgemm_tile(X, W, C);
}

__global__ __launch_bounds__(256) void t_kernel(const float* __restrict__ Wt){
    sgemm_tile(g_attn, Wt, g_t);
}

// ---------------- flash attention (fp32, unscaled logits) ----------------
// Block = (batch b, 64-query tile). 256 threads as 16x16.
// Thread owns S rows ty*4..ty*4+3 x cols tx*4..tx*4+3, and O rows ty*4..+3 x
// dims {c*16+tx : c in 0..15}.
#define ATT_SMEM ((256*68*2 + 64*256 + 64*68) * 4)

__global__ __launch_bounds__(256, 1) void attn_kernel(){
    extern __shared__ float sm[];
    float* Qst = sm;                  // [256][68]  Q^T (dim-major)
    float* Kst = sm + 256*68;         // [256][68]  K^T (dim-major)
    float* Vs  = Kst + 256*68;        // [64][256]  V row-major
    float* Ps  = Vs + 64*256;         // [64][68]   exp(S) tile

    const int b  = blockIdx.y;
    const int len = g_lens[b];
    const int q0 = blockIdx.x * 64;
    if (q0 >= len) return;            // output rows masked to zero anyway

    const int tid = threadIdx.x;
    const int tx = tid & 15, ty = tid >> 4;

    // load Q tile transposed: Qst[d][r] = q[q0+r][d]
    const float* qg = g_q + (size_t)(b*LL + q0)*DD;
    #pragma unroll 4
    for (int it = 0; it < 64; it++)
        Qst[tid*68 + it] = qg[(size_t)it*DD + tid];

    float mi[4], li[4], O[4][16];
    #pragma unroll
    for (int i = 0; i < 4; i++){
        mi[i] = -INFINITY; li[i] = 0.f;
        #pragma unroll
        for (int c = 0; c < 16; c++) O[i][c] = 0.f;
    }

    const int nkt = (len + 63) >> 6;
    for (int kt = 0; kt < nkt; kt++){
        __syncthreads();  // previous iter's Ps/Vs/Kst reads done (also Qst store)
        const float* kg = g_k + (size_t)(b*LL + kt*64)*DD;
        const float* vg = g_v + (size_t)(b*LL + kt*64)*DD;
        #pragma unroll 4
        for (int it = 0; it < 64; it++){
            Kst[tid*68 + it]        = kg[(size_t)it*DD + tid];
            Vs[(size_t)it*DD + tid] = vg[(size_t)it*DD + tid];
        }
        __syncthreads();

        // S = Q K^T  (64x64 tile, 4x4 per thread)
        float S[4][4] = {};
        #pragma unroll 8
        for (int kk = 0; kk < 256; kk++){
            float4 a = *(const float4*)&Qst[kk*68 + ty*4];
            float4 bb = *(const float4*)&Kst[kk*68 + tx*4];
            float a4[4] = {a.x, a.y, a.z, a.w};
            float b4[4] = {bb.x, bb.y, bb.z, bb.w};
            #pragma unroll
            for (int i = 0; i < 4; i++)
                #pragma unroll
                for (int j = 0; j < 4; j++)
                    S[i][j] = fmaf(a4[i], b4[j], S[i][j]);
        }

        // mask invalid keys
        const int jb = kt*64 + tx*4;
        if (jb + 3 >= len){
            #pragma unroll
            for (int j = 0; j < 4; j++)
                if (jb + j >= len)
                    #pragma unroll
                    for (int i = 0; i < 4; i++) S[i][j] = -INFINITY;
        }

        // online softmax per row (row group = 16 tx lanes, width-16 shuffles)
        #pragma unroll
        for (int i = 0; i < 4; i++){
            float rm = fmaxf(fmaxf(S[i][0], S[i][1]), fmaxf(S[i][2], S[i][3]));
            #pragma unroll
            for (int off = 8; off > 0; off >>= 1)
                rm = fmaxf(rm, __shfl_xor_sync(0xffffffffu, rm, off, 16));
            float mn = fmaxf(mi[i], rm);
            float rs = 0.f;
            #pragma unroll
            for (int j = 0; j < 4; j++){
                S[i][j] = __expf(S[i][j] - mn);
                rs += S[i][j];
            }
            #pragma unroll
            for (int off = 8; off > 0; off >>= 1)
                rs += __shfl_xor_sync(0xffffffffu, rs, off, 16);
            float sc = __expf(mi[i] - mn);
            li[i] = li[i]*sc + rs;
            mi[i] = mn;
            #pragma unroll
            for (int c = 0; c < 16; c++) O[i][c] *= sc;
            *(float4*)&Ps[(ty*4 + i)*68 + tx*4] =
                make_float4(S[i][0], S[i][1], S[i][2], S[i][3]);
        }
        __syncthreads();

        // O += P @ V
        #pragma unroll 2
        for (int j = 0; j < 64; j++){
            float p0 = Ps[(ty*4+0)*68 + j];
            float p1 = Ps[(ty*4+1)*68 + j];
            float p2 = Ps[(ty*4+2)*68 + j];
            float p3 = Ps[(ty*4+3)*68 + j];
            #pragma unroll
            for (int c = 0; c < 16; c++){
                float vv = Vs[(size_t)j*DD + c*16 + tx];
                O[0][c] = fmaf(p0, vv, O[0][c]);
                O[1][c] = fmaf(p1, vv, O[1][c]);
                O[2][c] = fmaf(p2, vv, O[2][c]);
                O[3][c] = fmaf(p3, vv, O[3][c]);
            }
        }
    }

    // epilogue: normalize and store
    float* og = g_attn + (size_t)(b*LL + q0)*DD;
    #pragma unroll
    for (int i = 0; i < 4; i++){
        float inv = 1.f / li[i];
        #pragma unroll
        for (int c = 0; c < 16; c++)
            og[(size_t)(ty*4 + i)*DD + c*16 + tx] = O[i][c] * inv;
    }
}

// ---------------- masked batchnorm: deterministic 2-stage reduction ----------------
__global__ void bn_partial(){
    const int c = threadIdx.x;            // channel
    const int row0 = blockIdx.x * 256;    // 128 blocks x 256 rows
    float s = 0.f, s2 = 0.f;
    for (int r = 0; r < 256; r++){
        const int row = row0 + r;
        const int b = row >> 12, l = row & (LL-1);
        if (l < g_lens[b]){
            float v = g_t[(size_t)row*DD + c];
            s += v; s2 += v*v;
        }
    }
    g_psum[blockIdx.x*DD + c] = s;
    g_psq [blockIdx.x*DD + c] = s2;
}

__global__ void bn_final(){
    const int c = threadIdx.x;
    float s = 0.f, s2 = 0.f;
    for (int i = 0; i < 128; i++){
        s  += g_psum[i*DD + c];
        s2 += g_psq [i*DD + c];
    }
    float n = 0.f;
    for (int b = 0; b < BB; b++) n += (float)g_lens[b];
    float mean = s / n;
    float var  = s2 / n - mean*mean;
    g_mean[c] = mean;
    g_rstd[c] = rsqrtf(var + 1e-4f);
}

// ---------------- BN + ReLU + residual + mask ----------------
__global__ void final_kernel(const float* __restrict__ x,
                             const float* __restrict__ gamma,
                             const float* __restrict__ beta,
                             float* __restrict__ out){
    const int row = blockIdx.x;
    const int c = threadIdx.x;
    const int b = row >> 12, l = row & (LL-1);
    const size_t idx = (size_t)row*DD + c;
    if (l < g_lens[b]){
        float t = g_t[idx];
        float y = fmaf(gamma[c]*(t - g_mean[c]), g_rstd[c], beta[c]);
        y = fmaxf(y, 0.f);
        out[idx] = x[idx] + y;
    } else {
        out[idx] = 0.f;   // exact zero, never 0 * garbage
    }
}

// ---------------- launch ----------------
extern "C" void kernel_launch(void* const* d_in, const int* in_sizes, int n_in,
                              void* d_out, int out_size){
    const float* x    = (const float*)d_in[0];
    const void*  mask = d_in[1];
    const float* Wq   = (const float*)d_in[2];
    const float* Wk   = (const float*)d_in[3];
    const float* Wv   = (const float*)d_in[4];
    const float* Wt   = (const float*)d_in[5];
    const float* gamma= (const float*)d_in[6];
    const float* beta = (const float*)d_in[7];
    float* out = (float*)d_out;

    cudaFuncSetAttribute(attn_kernel,
                         cudaFuncAttributeMaxDynamicSharedMemorySize, ATT_SMEM);

    lens_kernel<<<BB, 256>>>(mask);
    qkv_kernel<<<dim3(4, 512, 3), 256>>>(x, Wq, Wk, Wv);
    attn_kernel<<<dim3(64, BB), 256, ATT_SMEM>>>();
    t_kernel<<<dim3(4, 512, 1), 256>>>(Wt);
    bn_partial<<<128, 256>>>();
    bn_final<<<1, 256>>>();
    final_kernel<<<ML, 256>>>(x, gamma, beta, out);
    (void)in_sizes; (void)n_in; (void)out_size;
}

// round 10
// speedup vs baseline: 1.0110x; 1.0110x over previous
#include <cuda_runtime.h>
#include <math.h>
#include <stdint.h>

#define BB 8
#define LL 4096
#define DD 256
#define ML (BB*LL)

// ---------------- scratch (no allocations allowed) ----------------
__device__ float g_q[ML*DD];
__device__ float g_k[ML*DD];
__device__ float g_v[ML*DD];
__device__ float g_attn[ML*DD];
__device__ float g_t[ML*DD];
__device__ int   g_lens[BB];
__device__ float g_psum[128*DD];
__device__ float g_psq[128*DD];
__device__ float g_mean[DD];
__device__ float g_rstd[DD];

// ---------------- mask -> per-batch length ----------------
// mask rows are prefix masks (arange < len), len in [L/2, L].
// Dtype detection: if byte 1 of the buffer == 1 -> 1-byte bool/uint8 layout
// (mask[0][1] is true since len>=2048). Otherwise 4-byte elements (int32 or
// float32: any nonzero 32-bit pattern is truthy).
__global__ void lens_kernel(const void* maskp){
    const unsigned char* mb = (const unsigned char*)maskp;
    const int b = blockIdx.x;
    const bool bytemode = (mb[1] == 1);
    __shared__ int sh[256];
    int cnt = 0;
    for (int i = threadIdx.x; i < LL; i += 256){
        bool valid;
        if (bytemode) valid = (mb[b*LL + i] != 0);
        else          valid = (((const int*)maskp)[b*LL + i] != 0);
        cnt += valid ? 1 : 0;
    }
    sh[threadIdx.x] = cnt;
    __syncthreads();
    for (int s = 128; s > 0; s >>= 1){
        if (threadIdx.x < s) sh[threadIdx.x] += sh[threadIdx.x + s];
        __syncthreads();
    }
    if (threadIdx.x == 0) g_lens[b] = sh[0];
}

// ---------------- SGEMM: C[M,256] = A[M,256] @ W[256,256] ----------------
// 64x64 block tile, BK=16, 256 threads, 4x4 micro-tile per thread.
__device__ __forceinline__ void sgemm_tile(const float* __restrict__ A,
                                           const float* __restrict__ W,
                                           float* __restrict__ C){
    __shared__ float As[16][68];   // As[kk][m]  (A transposed in smem)
    __shared__ float Bs[16][68];   // Bs[kk][n]
    const int tid = threadIdx.x;
    const int tx = tid & 15, ty = tid >> 4;
    const int m0 = blockIdx.y * 64, n0 = blockIdx.x * 64;
    const int ar = tid >> 2, ac = (tid & 3) * 4;     // A load: row, col4
    const int bk = tid >> 4, bn = (tid & 15) * 4;    // B load: krow, ncol4
    float acc[4][4] = {};
    for (int k0 = 0; k0 < 256; k0 += 16){
        float4 av = *(const float4*)(A + (size_t)(m0 + ar)*DD + k0 + ac);
        As[ac+0][ar] = av.x; As[ac+1][ar] = av.y;
        As[ac+2][ar] = av.z; As[ac+3][ar] = av.w;
        float4 bv = *(const float4*)(W + (size_t)(k0 + bk)*DD + n0 + bn);
        *(float4*)&Bs[bk][bn] = bv;
        __syncthreads();
        #pragma unroll
        for (int kk = 0; kk < 16; kk++){
            float4 a = *(const float4*)&As[kk][ty*4];
            float4 b = *(const float4*)&Bs[kk][tx*4];
            float a4[4] = {a.x, a.y, a.z, a.w};
            float b4[4] = {b.x, b.y, b.z, b.w};
            #pragma unroll
            for (int i = 0; i < 4; i++)
                #pragma unroll
                for (int j = 0; j < 4; j++)
                    acc[i][j] = fmaf(a4[i], b4[j], acc[i][j]);
        }
        __syncthreads();
    }
    #pragma unroll
    for (int i = 0; i < 4; i++){
        float4 o = make_float4(acc[i][0], acc[i][1], acc[i][2], acc[i][3]);
        *(float4*)(C + (size_t)(m0 + ty*4 + i)*DD + n0 + tx*4) = o;
    }
}

__global__ __launch_bounds__(256) void qkv_kernel(const float* __restrict__ X,
                                                  const float* __restrict__ Wq,
                                                  const float* __restrict__ Wk,
                                                  const float* __restrict__ Wv){
    const float* W; float* C;
    if (blockIdx.z == 0){ W = Wq; C = g_q; }
    else if (blockIdx.z == 1){ W = Wk; C = g_k; }
    else { W = Wv; C = g_v; }
    sgemm_tile(X, W, C);
}

__global__ __launch_bounds__(256) void t_kernel(const float* __restrict__ Wt){
    sgemm_tile(g_attn, Wt, g_t);
}

// ---------------- flash attention (fp32, unscaled logits) ----------------
// Block = (batch b, 64-query tile). 256 threads as 16x16.
// Thread owns S rows ty*4..ty*4+3 x cols tx*4..tx*4+3, and O rows ty*4..+3 x
// dims {c*16+tx : c in 0..15}.
#define ATT_SMEM ((256*68*2 + 64*256 + 64*68) * 4)

__global__ __launch_bounds__(256, 1) void attn_kernel(){
    extern __shared__ float sm[];
    float* Qst = sm;                  // [256][68]  Q^T (dim-major)
    float* Kst = sm + 256*68;         // [256][68]  K^T (dim-major)
    float* Vs  = Kst + 256*68;        // [64][256]  V row-major
    float* Ps  = Vs + 64*256;         // [64][68]   exp(S) tile

    const int b  = blockIdx.y;
    const int len = g_lens[b];
    const int q0 = blockIdx.x * 64;
    if (q0 >= len) return;            // output rows masked to zero anyway

    const int tid = threadIdx.x;
    const int tx = tid & 15, ty = tid >> 4;

    // load Q tile transposed: Qst[d][r] = q[q0+r][d]
    const float* qg = g_q + (size_t)(b*LL + q0)*DD;
    #pragma unroll 4
    for (int it = 0; it < 64; it++)
        Qst[tid*68 + it] = qg[(size_t)it*DD + tid];

    float mi[4], li[4], O[4][16];
    #pragma unroll
    for (int i = 0; i < 4; i++){
        mi[i] = -INFINITY; li[i] = 0.f;
        #pragma unroll
        for (int c = 0; c < 16; c++) O[i][c] = 0.f;
    }

    const int nkt = (len + 63) >> 6;
    for (int kt = 0; kt < nkt; kt++){
        __syncthreads();  // previous iter's Ps/Vs/Kst reads done (also Qst store)
        const float* kg = g_k + (size_t)(b*LL + kt*64)*DD;
        const float* vg = g_v + (size_t)(b*LL + kt*64)*DD;
        #pragma unroll 4
        for (int it = 0; it < 64; it++){
            Kst[tid*68 + it]        = kg[(size_t)it*DD + tid];
            Vs[(size_t)it*DD + tid] = vg[(size_t)it*DD + tid];
        }
        __syncthreads();

        // S = Q K^T  (64x64 tile, 4x4 per thread)
        float S[4][4] = {};
        #pragma unroll 8
        for (int kk = 0; kk < 256; kk++){
            float4 a = *(const float4*)&Qst[kk*68 + ty*4];
            float4 bb = *(const float4*)&Kst[kk*68 + tx*4];
            float a4[4] = {a.x, a.y, a.z, a.w};
            float b4[4] = {bb.x, bb.y, bb.z, bb.w};
            #pragma unroll
            for (int i = 0; i < 4; i++)
                #pragma unroll
                for (int j = 0; j < 4; j++)
                    S[i][j] = fmaf(a4[i], b4[j], S[i][j]);
        }

        // mask invalid keys
        const int jb = kt*64 + tx*4;
        if (jb + 3 >= len){
            #pragma unroll
            for (int j = 0; j < 4; j++)
                if (jb + j >= len)
                    #pragma unroll
                    for (int i = 0; i < 4; i++) S[i][j] = -INFINITY;
        }

        // online softmax per row (row group = 16 tx lanes, width-16 shuffles)
        #pragma unroll
        for (int i = 0; i < 4; i++){
            float rm = fmaxf(fmaxf(S[i][0], S[i][1]), fmaxf(S[i][2], S[i][3]));
            #pragma unroll
            for (int off = 8; off > 0; off >>= 1)
                rm = fmaxf(rm, __shfl_xor_sync(0xffffffffu, rm, off, 16));
            float mn = fmaxf(mi[i], rm);
            float rs = 0.f;
            #pragma unroll
            for (int j = 0; j < 4; j++){
                S[i][j] = __expf(S[i][j] - mn);
                rs += S[i][j];
            }
            #pragma unroll
            for (int off = 8; off > 0; off >>= 1)
                rs += __shfl_xor_sync(0xffffffffu, rs, off, 16);
            float sc = __expf(mi[i] - mn);
            li[i] = li[i]*sc + rs;
            mi[i] = mn;
            #pragma unroll
            for (int c = 0; c < 16; c++) O[i][c] *= sc;
            *(float4*)&Ps[(ty*4 + i)*68 + tx*4] =
                make_float4(S[i][0], S[i][1], S[i][2], S[i][3]);
        }
        __syncthreads();

        // O += P @ V
        #pragma unroll 2
        for (int j = 0; j < 64; j++){
            float p0 = Ps[(ty*4+0)*68 + j];
            float p1 = Ps[(ty*4+1)*68 + j];
            float p2 = Ps[(ty*4+2)*68 + j];
            float p3 = Ps[(ty*4+3)*68 + j];
            #pragma unroll
            for (int c = 0; c < 16; c++){
                float vv = Vs[(size_t)j*DD + c*16 + tx];
                O[0][c] = fmaf(p0, vv, O[0][c]);
                O[1][c] = fmaf(p1, vv, O[1][c]);
                O[2][c] = fmaf(p2, vv, O[2][c]);
                O[3][c] = fmaf(p3, vv, O[3][c]);
            }
        }
    }

    // epilogue: normalize and store
    float* og = g_attn + (size_t)(b*LL + q0)*DD;
    #pragma unroll
    for (int i = 0; i < 4; i++){
        float inv = 1.f / li[i];
        #pragma unroll
        for (int c = 0; c < 16; c++)
            og[(size_t)(ty*4 + i)*DD + c*16 + tx] = O[i][c] * inv;
    }
}

// ---------------- masked batchnorm: deterministic 2-stage reduction ----------------
__global__ void bn_partial(){
    const int c = threadIdx.x;            // channel
    const int row0 = blockIdx.x * 256;    // 128 blocks x 256 rows
    float s = 0.f, s2 = 0.f;
    for (int r = 0; r < 256; r++){
        const int row = row0 + r;
        const int b = row >> 12, l = row & (LL-1);
        if (l < g_lens[b]){
            float v = g_t[(size_t)row*DD + c];
            s += v; s2 += v*v;
        }
    }
    g_psum[blockIdx.x*DD + c] = s;
    g_psq [blockIdx.x*DD + c] = s2;
}

__global__ void bn_final(){
    const int c = threadIdx.x;
    float s = 0.f, s2 = 0.f;
    for (int i = 0; i < 128; i++){
        s  += g_psum[i*DD + c];
        s2 += g_psq [i*DD + c];
    }
    float n = 0.f;
    for (int b = 0; b < BB; b++) n += (float)g_lens[b];
    float mean = s / n;
    float var  = s2 / n - mean*mean;
    g_mean[c] = mean;
    g_rstd[c] = rsqrtf(var + 1e-4f);
}

// ---------------- BN + ReLU + residual + mask ----------------
__global__ void final_kernel(const float* __restrict__ x,
                             const float* __restrict__ gamma,
                             const float* __restrict__ beta,
                             float* __restrict__ out){
    const int row = blockIdx.x;
    const int c = threadIdx.x;
    const int b = row >> 12, l = row & (LL-1);
    const size_t idx = (size_t)row*DD + c;
    if (l < g_lens[b]){
        float t = g_t[idx];
        float y = fmaf(gamma[c]*(t - g_mean[c]), g_rstd[c], beta[c]);
        y = fmaxf(y, 0.f);
        out[idx] = x[idx] + y;
    } else {
        out[idx] = 0.f;   // exact zero, never 0 * garbage
    }
}

// ---------------- launch ----------------
extern "C" void kernel_launch(void* const* d_in, const int* in_sizes, int n_in,
                              void* d_out, int out_size){
    const float* x    = (const float*)d_in[0];
    const void*  mask = d_in[1];
    const float* Wq   = (const float*)d_in[2];
    const float* Wk   = (const float*)d_in[3];
    const float* Wv   = (const float*)d_in[4];
    const float* Wt   = (const float*)d_in[5];
    const float* gamma= (const float*)d_in[6];
    const float* beta = (const float*)d_in[7];
    float* out = (float*)d_out;

    cudaFuncSetAttribute(attn_kernel,
                         cudaFuncAttributeMaxDynamicSharedMemorySize, ATT_SMEM);

    lens_kernel<<<BB, 256>>>(mask);
    qkv_kernel<<<dim3(4, 512, 3), 256>>>(x, Wq, Wk, Wv);
    attn_kernel<<<dim3(64, BB), 256, ATT_SMEM>>>();
    t_kernel<<<dim3(4, 512, 1), 256>>>(Wt);
    bn_partial<<<128, 256>>>();
    bn_final<<<1, 256>>>();
    final_kernel<<<ML, 256>>>(x, gamma, beta, out);
    (void)in_sizes; (void)n_in; (void)out_size;
}

// round 11
// speedup vs baseline: 1.0124x; 1.0014x over previous
#include <cuda_runtime.h>
#include <math.h>
#include <stdint.h>

#define BB 8
#define LL 4096
#define DD 256
#define ML (BB*LL)

// ---------------- scratch (no allocations allowed) ----------------
__device__ float g_q[ML*DD];
__device__ float g_k[ML*DD];
__device__ float g_v[ML*DD];
__device__ float g_attn[ML*DD];
__device__ float g_t[ML*DD];
__device__ int   g_lens[BB];
__device__ float g_psum[128*DD];
__device__ float g_psq[128*DD];
__device__ float g_mean[DD];
__device__ float g_rstd[DD];

// ---------------- mask -> per-batch length ----------------
// mask rows are prefix masks (arange < len), len in [L/2, L].
// Dtype detection: if byte 1 of the buffer == 1 -> 1-byte bool/uint8 layout
// (mask[0][1] is true since len>=2048). Otherwise 4-byte elements (int32 or
// float32: any nonzero 32-bit pattern is truthy).
__global__ void lens_kernel(const void* maskp){
    const unsigned char* mb = (const unsigned char*)maskp;
    const int b = blockIdx.x;
    const bool bytemode = (mb[1] == 1);
    __shared__ int sh[256];
    int cnt = 0;
    for (int i = threadIdx.x; i < LL; i += 256){
        bool valid;
        if (bytemode) valid = (mb[b*LL + i] != 0);
        else          valid = (((const int*)maskp)[b*LL + i] != 0);
        cnt += valid ? 1 : 0;
    }
    sh[threadIdx.x] = cnt;
    __syncthreads();
    for (int s = 128; s > 0; s >>= 1){
        if (threadIdx.x < s) sh[threadIdx.x] += sh[threadIdx.x + s];
        __syncthreads();
    }
    if (threadIdx.x == 0) g_lens[b] = sh[0];
}

// ---------------- SGEMM: C[M,256] = A[M,256] @ W[256,256] ----------------
// 64x64 block tile, BK=16, 256 threads, 4x4 micro-tile per thread.
__device__ __forceinline__ void sgemm_tile(const float* __restrict__ A,
                                           const float* __restrict__ W,
                                           float* __restrict__ C){
    __shared__ float As[16][68];   // As[kk][m]  (A transposed in smem)
    __shared__ float Bs[16][68];   // Bs[kk][n]
    const int tid = threadIdx.x;
    const int tx = tid & 15, ty = tid >> 4;
    const int m0 = blockIdx.y * 64, n0 = blockIdx.x * 64;
    const int ar = tid >> 2, ac = (tid & 3) * 4;     // A load: row, col4
    const int bk = tid >> 4, bn = (tid & 15) * 4;    // B load: krow, ncol4
    float acc[4][4] = {};
    for (int k0 = 0; k0 < 256; k0 += 16){
        float4 av = *(const float4*)(A + (size_t)(m0 + ar)*DD + k0 + ac);
        As[ac+0][ar] = av.x; As[ac+1][ar] = av.y;
        As[ac+2][ar] = av.z; As[ac+3][ar] = av.w;
        float4 bv = *(const float4*)(W + (size_t)(k0 + bk)*DD + n0 + bn);
        *(float4*)&Bs[bk][bn] = bv;
        __syncthreads();
        #pragma unroll
        for (int kk = 0; kk < 16; kk++){
            float4 a = *(const float4*)&As[kk][ty*4];
            float4 b = *(const float4*)&Bs[kk][tx*4];
            float a4[4] = {a.x, a.y, a.z, a.w};
            float b4[4] = {b.x, b.y, b.z, b.w};
            #pragma unroll
            for (int i = 0; i < 4; i++)
                #pragma unroll
                for (int j = 0; j < 4; j++)
                    acc[i][j] = fmaf(a4[i], b4[j], acc[i][j]);
        }
        __syncthreads();
    }
    #pragma unroll
    for (int i = 0; i < 4; i++){
        float4 o = make_float4(acc[i][0], acc[i][1], acc[i][2], acc[i][3]);
        *(float4*)(C + (size_t)(m0 + ty*4 + i)*DD + n0 + tx*4) = o;
    }
}

__global__ __launch_bounds__(256) void qkv_kernel(const float* __restrict__ X,
                                                  const float* __restrict__ Wq,
                                                  const float* __restrict__ Wk,
                                                  const float* __restrict__ Wv){
    const float* W; float* C;
    if (blockIdx.z == 0){ W = Wq; C = g_q; }
    else if (blockIdx.z == 1){ W = Wk; C = g_k; }
    else { W = Wv; C = g_v; }
    sgemm_tile(X, W, C);
}

__global__ __launch_bounds__(256) void t_kernel(const float* __restrict__ Wt){
    sgemm_tile(g_attn, Wt, g_t);
}

// ---------------- flash attention (fp32, unscaled logits) ----------------
// Block = (batch b, 64-query tile). 256 threads as 16x16.
// Thread owns S rows ty*4..ty*4+3 x cols tx*4..tx*4+3, and O rows ty*4..+3 x
// dims {c*16+tx : c in 0..15}.
#define ATT_SMEM ((256*68*2 + 64*256 + 64*68) * 4)

__global__ __launch_bounds__(256, 1) void attn_kernel(){
    extern __shared__ float sm[];
    float* Qst = sm;                  // [256][68]  Q^T (dim-major)
    float* Kst = sm + 256*68;         // [256][68]  K^T (dim-major)
    float* Vs  = Kst + 256*68;        // [64][256]  V row-major
    float* Ps  = Vs + 64*256;         // [64][68]   exp(S) tile

    const int b  = blockIdx.y;
    const int len = g_lens[b];
    const int q0 = blockIdx.x * 64;
    if (q0 >= len) return;            // output rows masked to zero anyway

    const int tid = threadIdx.x;
    const int tx = tid & 15, ty = tid >> 4;

    // load Q tile transposed: Qst[d][r] = q[q0+r][d]
    const float* qg = g_q + (size_t)(b*LL + q0)*DD;
    #pragma unroll 4
    for (int it = 0; it < 64; it++)
        Qst[tid*68 + it] = qg[(size_t)it*DD + tid];

    float mi[4], li[4], O[4][16];
    #pragma unroll
    for (int i = 0; i < 4; i++){
        mi[i] = -INFINITY; li[i] = 0.f;
        #pragma unroll
        for (int c = 0; c < 16; c++) O[i][c] = 0.f;
    }

    const int nkt = (len + 63) >> 6;
    for (int kt = 0; kt < nkt; kt++){
        __syncthreads();  // previous iter's Ps/Vs/Kst reads done (also Qst store)
        const float* kg = g_k + (size_t)(b*LL + kt*64)*DD;
        const float* vg = g_v + (size_t)(b*LL + kt*64)*DD;
        #pragma unroll 4
        for (int it = 0; it < 64; it++){
            Kst[tid*68 + it]        = kg[(size_t)it*DD + tid];
            Vs[(size_t)it*DD + tid] = vg[(size_t)it*DD + tid];
        }
        __syncthreads();

        // S = Q K^T  (64x64 tile, 4x4 per thread)
        float S[4][4] = {};
        #pragma unroll 8
        for (int kk = 0; kk < 256; kk++){
            float4 a = *(const float4*)&Qst[kk*68 + ty*4];
            float4 bb = *(const float4*)&Kst[kk*68 + tx*4];
            float a4[4] = {a.x, a.y, a.z, a.w};
            float b4[4] = {bb.x, bb.y, bb.z, bb.w};
            #pragma unroll
            for (int i = 0; i < 4; i++)
                #pragma unroll
                for (int j = 0; j < 4; j++)
                    S[i][j] = fmaf(a4[i], b4[j], S[i][j]);
        }

        // mask invalid keys
        const int jb = kt*64 + tx*4;
        if (jb + 3 >= len){
            #pragma unroll
            for (int j = 0; j < 4; j++)
                if (jb + j >= len)
                    #pragma unroll
                    for (int i = 0; i < 4; i++) S[i][j] = -INFINITY;
        }

        // online softmax per row (row group = 16 tx lanes, width-16 shuffles)
        #pragma unroll
        for (int i = 0; i < 4; i++){
            float rm = fmaxf(fmaxf(S[i][0], S[i][1]), fmaxf(S[i][2], S[i][3]));
            #pragma unroll
            for (int off = 8; off > 0; off >>= 1)
                rm = fmaxf(rm, __shfl_xor_sync(0xffffffffu, rm, off, 16));
            float mn = fmaxf(mi[i], rm);
            float rs = 0.f;
            #pragma unroll
            for (int j = 0; j < 4; j++){
                S[i][j] = __expf(S[i][j] - mn);
                rs += S[i][j];
            }
            #pragma unroll
            for (int off = 8; off > 0; off >>= 1)
                rs += __shfl_xor_sync(0xffffffffu, rs, off, 16);
            float sc = __expf(mi[i] - mn);
            li[i] = li[i]*sc + rs;
            mi[i] = mn;
            #pragma unroll
            for (int c = 0; c < 16; c++) O[i][c] *= sc;
            *(float4*)&Ps[(ty*4 + i)*68 + tx*4] =
                make_float4(S[i][0], S[i][1], S[i][2], S[i][3]);
        }
        __syncthreads();

        // O += P @ V
        #pragma unroll 2
        for (int j = 0; j < 64; j++){
            float p0 = Ps[(ty*4+0)*68 + j];
            float p1 = Ps[(ty*4+1)*68 + j];
            float p2 = Ps[(ty*4+2)*68 + j];
            float p3 = Ps[(ty*4+3)*68 + j];
            #pragma unroll
            for (int c = 0; c < 16; c++){
                float vv = Vs[(size_t)j*DD + c*16 + tx];
                O[0][c] = fmaf(p0, vv, O[0][c]);
                O[1][c] = fmaf(p1, vv, O[1][c]);
                O[2][c] = fmaf(p2, vv, O[2][c]);
                O[3][c] = fmaf(p3, vv, O[3][c]);
            }
        }
    }

    // epilogue: normalize and store
    float* og = g_attn + (size_t)(b*LL + q0)*DD;
    #pragma unroll
    for (int i = 0; i < 4; i++){
        float inv = 1.f / li[i];
        #pragma unroll
        for (int c = 0; c < 16; c++)
            og[(size_t)(ty*4 + i)*DD + c*16 + tx] = O[i][c] * inv;
    }
}

// ---------------- masked batchnorm: deterministic 2-stage reduction ----------------
__global__ void bn_partial(){
    const int c = threadIdx.x;            // channel
    const int row0 = blockIdx.x * 256;    // 128 blocks x 256 rows
    float s = 0.f, s2 = 0.f;
    for (int r = 0; r < 256; r++){
        const int row = row0 + r;
        const int b = row >> 12, l = row & (LL-1);
        if (l < g_lens[b]){
            float v = g_t[(size_t)row*DD + c];
            s += v; s2 += v*v;
        }
    }
    g_psum[blockIdx.x*DD + c] = s;
    g_psq [blockIdx.x*DD + c] = s2;
}

__global__ void bn_final(){
    const int c = threadIdx.x;
    float s = 0.f, s2 = 0.f;
    for (int i = 0; i < 128; i++){
        s  += g_psum[i*DD + c];
        s2 += g_psq [i*DD + c];
    }
    float n = 0.f;
    for (int b = 0; b < BB; b++) n += (float)g_lens[b];
    float mean = s / n;
    float var  = s2 / n - mean*mean;
    g_mean[c] = mean;
    g_rstd[c] = rsqrtf(var + 1e-4f);
}

// ---------------- BN + ReLU + residual + mask ----------------
__global__ void final_kernel(const float* __restrict__ x,
                             const float* __restrict__ gamma,
                             const float* __restrict__ beta,
                             float* __restrict__ out){
    const int row = blockIdx.x;
    const int c = threadIdx.x;
    const int b = row >> 12, l = row & (LL-1);
    const size_t idx = (size_t)row*DD + c;
    if (l < g_lens[b]){
        float t = g_t[idx];
        float y = fmaf(gamma[c]*(t - g_mean[c]), g_rstd[c], beta[c]);
        y = fmaxf(y, 0.f);
        out[idx] = x[idx] + y;
    } else {
        out[idx] = 0.f;   // exact zero, never 0 * garbage
    }
}

// ---------------- launch ----------------
extern "C" void kernel_launch(void* const* d_in, const int* in_sizes, int n_in,
                              void* d_out, int out_size){
    const float* x    = (const float*)d_in[0];
    const void*  mask = d_in[1];
    const float* Wq   = (const float*)d_in[2];
    const float* Wk   = (const float*)d_in[3];
    const float* Wv   = (const float*)d_in[4];
    const float* Wt   = (const float*)d_in[5];
    const float* gamma= (const float*)d_in[6];
    const float* beta = (const float*)d_in[7];
    float* out = (float*)d_out;

    cudaFuncSetAttribute(attn_kernel,
                         cudaFuncAttributeMaxDynamicSharedMemorySize, ATT_SMEM);

    lens_kernel<<<BB, 256>>>(mask);
    qkv_kernel<<<dim3(4, 512, 3), 256>>>(x, Wq, Wk, Wv);
    attn_kernel<<<dim3(64, BB), 256, ATT_SMEM>>>();
    t_kernel<<<dim3(4, 512, 1), 256>>>(Wt);
    bn_partial<<<128, 256>>>();
    bn_final<<<1, 256>>>();
    final_kernel<<<ML, 256>>>(x, gamma, beta, out);
    (void)in_sizes; (void)n_in; (void)out_size;
}